// round 10
// baseline (speedup 1.0000x reference)
#include <cuda_runtime.h>
#include <cstdint>

#define Bc      131072
#define TILE    32
#define NTHREADS 256
// transposed activation layout: hT[k][m], k=0..255, m=0..31 (32 floats/row, XOR-swizzled)

// ---------------- device scratch (no allocations allowed) ----------------
__device__ float g_W1T[256 * 256];
__device__ float g_W2T[256 * 256];
__device__ float g_W0T[256 * 12];   // [j][k], k padded 11->12

__global__ void transpose_kernel(const float* __restrict__ W0,
                                 const float* __restrict__ W1,
                                 const float* __restrict__ W2) {
    int i = blockIdx.x;      // 0..255 (source row)
    int j = threadIdx.x;     // 0..255 (source col)
    g_W1T[j * 256 + i] = W1[i * 256 + j];
    g_W2T[j * 256 + i] = W2[i * 256 + j];
    if (i < 11)  g_W0T[j * 12 + i] = W0[i * 256 + j];
    if (i == 11) g_W0T[j * 12 + 11] = 0.0f;
}

// accurate-enough tanh: 2 MUFU (EX2 + RCP), abs err ~1e-7
__device__ __forceinline__ float tanh_fast(float x) {
    float xc = fminf(fmaxf(x, -15.0f), 15.0f);
    float e  = __expf(2.0f * xc);
    return __fdividef(e - 1.0f, e + 1.0f);
}

// packed f32x2 helpers
#define FMA2(d, a, b, c) \
    asm("fma.rn.f32x2 %0, %1, %2, %3;" : "=l"(d) : "l"(a), "l"(b), "l"(c))
#define BCAST2(d, s) \
    asm("mov.b64 %0, {%1, %1};" : "=l"(d) : "r"(s))
#define UNPACK2(lo, hi, s) \
    asm("mov.b64 {%0, %1}, %2;" : "=r"(lo), "=r"(hi) : "l"(s))

// swizzle: element (idx, m) lives at  idx*32 + (m ^ (4*((idx>>2)&7)))
__device__ __forceinline__ int swz_f(int idx) { return 4 * ((idx >> 2) & 7); }

#define M_TANH 0   // hout = tanh(acc + bias)
#define M_D3   1   // h3 = tanh(acc + bias); hout = W3[j] * (1 - h3^2)
#define M_BWD  2   // hout = acc * (1 - hout^2)   (in-place, hout holds forward act)

// do 16 FFMA2 for one k-step: rows packed in pairs (hA, hB), cols j0..j0+3 (wv)
#define KSTEP(hA, hB, wv)                                              \
    do {                                                               \
        unsigned long long b0, b1, b2, b3;                             \
        BCAST2(b0, __float_as_uint((wv).x));                           \
        BCAST2(b1, __float_as_uint((wv).y));                           \
        BCAST2(b2, __float_as_uint((wv).z));                           \
        BCAST2(b3, __float_as_uint((wv).w));                           \
        FMA2(acc2[0][0], (hA).x, b0, acc2[0][0]);                      \
        FMA2(acc2[1][0], (hA).y, b0, acc2[1][0]);                      \
        FMA2(acc2[2][0], (hB).x, b0, acc2[2][0]);                      \
        FMA2(acc2[3][0], (hB).y, b0, acc2[3][0]);                      \
        FMA2(acc2[0][1], (hA).x, b1, acc2[0][1]);                      \
        FMA2(acc2[1][1], (hA).y, b1, acc2[1][1]);                      \
        FMA2(acc2[2][1], (hB).x, b1, acc2[2][1]);                      \
        FMA2(acc2[3][1], (hB).y, b1, acc2[3][1]);                      \
        FMA2(acc2[0][2], (hA).x, b2, acc2[0][2]);                      \
        FMA2(acc2[1][2], (hA).y, b2, acc2[1][2]);                      \
        FMA2(acc2[2][2], (hB).x, b2, acc2[2][2]);                      \
        FMA2(acc2[3][2], (hB).y, b2, acc2[3][2]);                      \
        FMA2(acc2[0][3], (hA).x, b3, acc2[0][3]);                      \
        FMA2(acc2[1][3], (hA).y, b3, acc2[1][3]);                      \
        FMA2(acc2[2][3], (hB).x, b3, acc2[2][3]);                      \
        FMA2(acc2[3][3], (hB).y, b3, acc2[3][3]);                      \
    } while (0)

// 32x256 <- 32x256 @ 256x256 ; 256 threads, per-thread tile 8 rows x 4 cols,
// rows packed in pairs for fma.rn.f32x2. Activations transposed+swizzled in SMEM.
// Activation LDS is double-buffered at HALF-CHUNK granularity: each pair of LDS.128
// has a >=32-FFMA2 (~64 cyc) shadow before first consumption, well above the 29-cyc
// LDS latency even with lockstep warps.
template <int MODE>
__device__ __forceinline__ void gemm256(const float* __restrict__ Wg,
                                        const float* __restrict__ bias,
                                        const float* __restrict__ w3,
                                        const float* __restrict__ hin,
                                        float* hout, int tid) {
    const int tx = tid & 63, ty = tid >> 6;   // ty: 0..3
    const int j0 = tx * 4, m0 = ty * 8;
    const int fj = 4 * (tx & 7);              // swizzle for output cols (j0+c)>>2 == tx

    unsigned long long acc2[4][4];            // [row-pair][col]
#pragma unroll
    for (int p = 0; p < 4; p++)
#pragma unroll
        for (int c = 0; c < 4; c++) acc2[p][c] = 0ULL;

    float4 wcur[4];
#pragma unroll
    for (int kk = 0; kk < 4; kk++)
        wcur[kk] = *(const float4*)(Wg + (size_t)kk * 256 + j0);

    // preload first half-chunk activations (k=0,1 ; swizzle offset 0 for chunk 0)
    ulonglong2 hA0, hB0, hA1, hB1;
    {
        const int pma0 = m0;                  // swz_f(0)==0
        hA0 = *(const ulonglong2*)(hin + 0 * 32 + pma0);
        hB0 = *(const ulonglong2*)(hin + 0 * 32 + (pma0 ^ 4));
        hA1 = *(const ulonglong2*)(hin + 1 * 32 + pma0);
        hB1 = *(const ulonglong2*)(hin + 1 * 32 + (pma0 ^ 4));
    }

#pragma unroll 1
    for (int k4 = 0; k4 < 256; k4 += 4) {
        const int fk  = swz_f(k4);
        const int pma = m0 ^ fk;              // rows m0..m0+3 (this chunk)
        const int pmb = pma ^ 4;

        const int k4n  = (k4 + 4) & 255;      // in-bounds wrap
        const int pman = m0 ^ swz_f(k4n);
        const int pmbn = pman ^ 4;

        // issue second half-chunk LDS (consumed after 32 FFMA2)
        ulonglong2 hA2 = *(const ulonglong2*)(hin + (k4 + 2) * 32 + pma);
        ulonglong2 hB2 = *(const ulonglong2*)(hin + (k4 + 2) * 32 + pmb);
        ulonglong2 hA3 = *(const ulonglong2*)(hin + (k4 + 3) * 32 + pma);
        ulonglong2 hB3 = *(const ulonglong2*)(hin + (k4 + 3) * 32 + pmb);

        // issue next chunk's weight LDG (consumed next iteration)
        float4 wnext[4];
#pragma unroll
        for (int kk = 0; kk < 4; kk++)
            wnext[kk] = *(const float4*)(Wg + (size_t)(k4n + kk) * 256 + j0);

        // first half FMAs (shadow for the LDS issued above)
        KSTEP(hA0, hB0, wcur[0]);
        KSTEP(hA1, hB1, wcur[1]);

        // issue next chunk's first half-chunk LDS (consumed next iteration)
        hA0 = *(const ulonglong2*)(hin + k4n * 32 + pman);
        hB0 = *(const ulonglong2*)(hin + k4n * 32 + pmbn);
        hA1 = *(const ulonglong2*)(hin + (k4n + 1) * 32 + pman);
        hB1 = *(const ulonglong2*)(hin + (k4n + 1) * 32 + pmbn);

        // second half FMAs
        KSTEP(hA2, hB2, wcur[2]);
        KSTEP(hA3, hB3, wcur[3]);

#pragma unroll
        for (int kk = 0; kk < 4; kk++) wcur[kk] = wnext[kk];
    }

    // unpack accumulators: vals[c][r] for rows m0+r
    float vals[4][8];
#pragma unroll
    for (int p = 0; p < 4; p++)
#pragma unroll
        for (int c = 0; c < 4; c++) {
            unsigned int lo, hi;
            UNPACK2(lo, hi, acc2[p][c]);
            vals[c][2 * p + 0] = __uint_as_float(lo);
            vals[c][2 * p + 1] = __uint_as_float(hi);
        }

    const int pj  = m0 ^ fj;                  // output run bases (4-aligned)
    const int pjb = pj ^ 4;

    if (MODE == M_TANH || MODE == M_D3) {
        float4 bjv = *(const float4*)(bias + j0);
        float bjc[4] = {bjv.x, bjv.y, bjv.z, bjv.w};
        float w3c[4];
        if (MODE == M_D3) {
            float4 w3v = *(const float4*)(w3 + j0);
            w3c[0] = w3v.x; w3c[1] = w3v.y; w3c[2] = w3v.z; w3c[3] = w3v.w;
        }
#pragma unroll
        for (int c = 0; c < 4; c++) {
            float z[8];
#pragma unroll
            for (int r = 0; r < 8; r++) {
                float h = tanh_fast(vals[c][r] + bjc[c]);
                z[r] = (MODE == M_TANH) ? h : (w3c[c] * (1.0f - h * h));
            }
            float* rowp = hout + (j0 + c) * 32;
            *(float4*)(rowp + pj)  = make_float4(z[0], z[1], z[2], z[3]);
            *(float4*)(rowp + pjb) = make_float4(z[4], z[5], z[6], z[7]);
        }
    } else {  // M_BWD: in-place dz = acc * (1 - h^2)
#pragma unroll
        for (int c = 0; c < 4; c++) {
            float* rowp = hout + (j0 + c) * 32;
            float4 ha = *(const float4*)(rowp + pj);
            float4 hb = *(const float4*)(rowp + pjb);
            float4 va, vb;
            va.x = vals[c][0] * (1.0f - ha.x * ha.x);
            va.y = vals[c][1] * (1.0f - ha.y * ha.y);
            va.z = vals[c][2] * (1.0f - ha.z * ha.z);
            va.w = vals[c][3] * (1.0f - ha.w * ha.w);
            vb.x = vals[c][4] * (1.0f - hb.x * hb.x);
            vb.y = vals[c][5] * (1.0f - hb.y * hb.y);
            vb.z = vals[c][6] * (1.0f - hb.z * hb.z);
            vb.w = vals[c][7] * (1.0f - hb.w * hb.w);
            *(float4*)(rowp + pj)  = va;
            *(float4*)(rowp + pjb) = vb;
        }
    }
}

__global__ void __launch_bounds__(NTHREADS, 2) ode_kernel(
    const float* __restrict__ v,  const float* __restrict__ w,
    const float* __restrict__ x,  const float* __restrict__ q,
    const float* __restrict__ W0, const float* __restrict__ b0,
    const float* __restrict__ W1, const float* __restrict__ b1,
    const float* __restrict__ W2, const float* __restrict__ b2,
    const float* __restrict__ W3,
    float* __restrict__ out) {
    extern __shared__ float smem[];
    float* h1s = smem;                    // hT layout [256][32]
    float* h2s = h1s + 256 * 32;
    float* d3s = h2s + 256 * 32;
    float* rqs = d3s + 256 * 32;          // [32][12] : r(3), qn0(4), qn1(4)
    float* grs = rqs + TILE * 12;         // [32][12] : grad_rq

    const int tid = threadIdx.x;
    const size_t row0 = (size_t)blockIdx.x * TILE;

    // ---- dxdt = v (pure copy, coalesced) ----
    if (tid < TILE * 6) {
        const size_t base = row0 * 6;
        out[(size_t)12 * Bc + base + tid] = v[base + tid];
    }

    // ---- build rq = [r, qn0, qn1] ----
    if (tid < TILE) {
        int m = tid;
        size_t g = row0 + m;
        float4 qa = *(const float4*)(q + g * 8);
        float4 qb = *(const float4*)(q + g * 8 + 4);
        float n0 = rsqrtf(qa.x * qa.x + qa.y * qa.y + qa.z * qa.z + qa.w * qa.w);
        float n1 = rsqrtf(qb.x * qb.x + qb.y * qb.y + qb.z * qb.z + qb.w * qb.w);
        const float* xp = x + g * 6;
        float* rp = rqs + m * 12;
        rp[0] = xp[3] - xp[0];
        rp[1] = xp[4] - xp[1];
        rp[2] = xp[5] - xp[2];
        rp[3] = qa.x * n0; rp[4] = qa.y * n0; rp[5] = qa.z * n0; rp[6] = qa.w * n0;
        rp[7] = qb.x * n1; rp[8] = qb.y * n1; rp[9] = qb.z * n1; rp[10] = qb.w * n1;
        rp[11] = 0.0f;
    }
    __syncthreads();

    // ---- layer 0: h1T[j][m] = tanh(rq[m] . W0[:,j] + b0[j]); one neuron per thread ----
    {
        int j = tid;
        float wcol[11];
#pragma unroll
        for (int k = 0; k < 11; k++) wcol[k] = W0[k * 256 + j];
        float bb = b0[j];
        float z[32];
#pragma unroll 4
        for (int m = 0; m < TILE; m++) {
            const float* rp = rqs + m * 12;
            float zz = bb;
#pragma unroll
            for (int k = 0; k < 11; k++) zz = fmaf(rp[k], wcol[k], zz);
            z[m] = tanh_fast(zz);
        }
        const int f = swz_f(j);
        float* rowp = h1s + j * 32;
#pragma unroll
        for (int mr = 0; mr < 32; mr += 4) {
            int pr = mr ^ f;   // 4-aligned physical base holding logical rows mr..mr+3
            *(float4*)(rowp + pr) = make_float4(z[mr], z[mr + 1], z[mr + 2], z[mr + 3]);
        }
    }
    __syncthreads();

    gemm256<M_TANH>(W1, b1, nullptr, h1s, h2s, tid);         // h2 = tanh(h1 W1 + b1)
    __syncthreads();
    gemm256<M_D3>(W2, b2, W3, h2s, d3s, tid);                // dz3 = W3*(1-h3^2)
    __syncthreads();
    gemm256<M_BWD>(g_W2T, nullptr, nullptr, d3s, h2s, tid);  // dz2 (in-place over h2)
    __syncthreads();
    gemm256<M_BWD>(g_W1T, nullptr, nullptr, h2s, h1s, tid);  // dz1 (in-place over h1)
    __syncthreads();

    // ---- grad_rq[k] = sum_j W0[k][j] * dz1[j] ; 8 threads per row ----
    {
        int m = tid >> 3, kq = tid & 7;
        float a[11];
#pragma unroll
        for (int k = 0; k < 11; k++) a[k] = 0.0f;
        int jb = kq * 32;
#pragma unroll 4
        for (int j = jb; j < jb + 32; j++) {
            float d = h1s[j * 32 + (m ^ swz_f(j))];
            float4 wA = *(const float4*)(g_W0T + j * 12);
            float4 wB = *(const float4*)(g_W0T + j * 12 + 4);
            float4 wC = *(const float4*)(g_W0T + j * 12 + 8);
            a[0] = fmaf(d, wA.x, a[0]); a[1] = fmaf(d, wA.y, a[1]);
            a[2] = fmaf(d, wA.z, a[2]); a[3] = fmaf(d, wA.w, a[3]);
            a[4] = fmaf(d, wB.x, a[4]); a[5] = fmaf(d, wB.y, a[5]);
            a[6] = fmaf(d, wB.z, a[6]); a[7] = fmaf(d, wB.w, a[7]);
            a[8] = fmaf(d, wC.x, a[8]); a[9] = fmaf(d, wC.y, a[9]);
            a[10] = fmaf(d, wC.z, a[10]);
        }
#pragma unroll
        for (int k = 0; k < 11; k++) {
            a[k] += __shfl_xor_sync(0xffffffffu, a[k], 1);
            a[k] += __shfl_xor_sync(0xffffffffu, a[k], 2);
            a[k] += __shfl_xor_sync(0xffffffffu, a[k], 4);
        }
        if (kq == 0) {
#pragma unroll
            for (int k = 0; k < 11; k++) grs[m * 12 + k] = a[k];
        }
    }
    __syncthreads();

    // ---- epilogue: quaternion dynamics + outputs (one thread per (row, particle)) ----
    if (tid < TILE * 2) {
        int m = tid >> 1, p = tid & 1;
        size_t g = row0 + m;
        size_t e = g * 2 + p;
        const float* rp = rqs + m * 12;
        const float* gp = grs + m * 12;
        float q0 = rp[3 + 4 * p], q1 = rp[4 + 4 * p], q2 = rp[5 + 4 * p], q3 = rp[6 + 4 * p];
        float gq0 = gp[3 + 4 * p], gq1 = gp[4 + 4 * p], gq2 = gp[5 + 4 * p], gq3 = gp[6 + 4 * p];
        float wx = w[e * 3 + 0], wy = w[e * 3 + 1], wz = w[e * 3 + 2];

        // dqdt = 0.5 * qn * (0, w)   (real-first Hamilton product)
        float dq0 = -0.5f * (q1 * wx + q2 * wy + q3 * wz);
        float dq1 =  0.5f * (q0 * wx + q2 * wz - q3 * wy);
        float dq2 =  0.5f * (q0 * wy - q1 * wz + q3 * wx);
        float dq3 =  0.5f * (q0 * wz + q1 * wy - q2 * wx);
        out[(size_t)18 * Bc + e * 4 + 0] = dq0;
        out[(size_t)18 * Bc + e * 4 + 1] = dq1;
        out[(size_t)18 * Bc + e * 4 + 2] = dq2;
        out[(size_t)18 * Bc + e * 4 + 3] = dq3;

        float Gq[3][4] = {{-q1,  q0,  q3, -q2},
                          {-q2, -q3,  q0,  q1},
                          {-q3,  q2, -q1,  q0}};
        float Gd[3][4] = {{-dq1,  dq0,  dq3, -dq2},
                          {-dq2, -dq3,  dq0,  dq1},
                          {-dq3,  dq2, -dq1,  dq0}};
        float l0 = wx * 1.0f, l1 = wy * 2.0f, l2 = wz * 3.0f;
        float gqv[4] = {gq0, gq1, gq2, gq3};
#pragma unroll
        for (int i = 0; i < 3; i++) {
            float O0 = 2.0f * (Gq[i][0] * Gd[0][0] + Gq[i][1] * Gd[0][1] + Gq[i][2] * Gd[0][2] + Gq[i][3] * Gd[0][3]);
            float O1 = 2.0f * (Gq[i][0] * Gd[1][0] + Gq[i][1] * Gd[1][1] + Gq[i][2] * Gd[1][2] + Gq[i][3] * Gd[1][3]);
            float O2 = 2.0f * (Gq[i][0] * Gd[2][0] + Gq[i][1] * Gd[2][1] + Gq[i][2] * Gd[2][2] + Gq[i][3] * Gd[2][3]);
            float t = -(O0 * l0 + O1 * l1 + O2 * l2)
                      - 0.5f * (Gq[i][0] * gqv[0] + Gq[i][1] * gqv[1] + Gq[i][2] * gqv[2] + Gq[i][3] * gqv[3]);
            out[(size_t)6 * Bc + e * 3 + i] = t / (float)(i + 1);
        }

        // dvdt = +-(grad_r + harm)/MASS
        float r0 = rp[0], r1 = rp[1], r2 = rp[2];
        float rn = sqrtf(r0 * r0 + r1 * r1 + r2 * r2);
        float coef = 100.0f * (rn - 1.0f) / rn;
        float sgn = p ? -1.0f : 1.0f;
        out[e * 3 + 0] = sgn * (gp[0] + coef * r0) / 7.0f;
        out[e * 3 + 1] = sgn * (gp[1] + coef * r1) / 7.0f;
        out[e * 3 + 2] = sgn * (gp[2] + coef * r2) / 7.0f;
    }
}

extern "C" void kernel_launch(void* const* d_in, const int* in_sizes, int n_in,
                              void* d_out, int out_size) {
    const float* v  = (const float*)d_in[0];
    const float* w  = (const float*)d_in[1];
    const float* x  = (const float*)d_in[2];
    const float* q  = (const float*)d_in[3];
    const float* W0 = (const float*)d_in[4];
    const float* b0 = (const float*)d_in[5];
    const float* W1 = (const float*)d_in[6];
    const float* b1 = (const float*)d_in[7];
    const float* W2 = (const float*)d_in[8];
    const float* b2 = (const float*)d_in[9];
    const float* W3 = (const float*)d_in[10];
    float* out = (float*)d_out;

    constexpr size_t SMEM_BYTES = (size_t)(3 * 256 * 32 + 2 * TILE * 12) * sizeof(float);
    cudaFuncSetAttribute(ode_kernel, cudaFuncAttributeMaxDynamicSharedMemorySize,
                         (int)SMEM_BYTES);

    transpose_kernel<<<256, 256>>>(W0, W1, W2);
    ode_kernel<<<Bc / TILE, NTHREADS, SMEM_BYTES>>>(v, w, x, q, W0, b0, W1, b1,
                                                    W2, b2, W3, out);
}

// round 11
// speedup vs baseline: 1.0325x; 1.0325x over previous
#include <cuda_runtime.h>
#include <cstdint>

#define Bc      131072
#define TILE    32
#define NTHREADS 256
// transposed activation layout: hT[k][m], k=0..255, m=0..31 (32 floats/row, XOR-swizzled)

// ---------------- device scratch (no allocations allowed) ----------------
__device__ float g_W1T[256 * 256];
__device__ float g_W2T[256 * 256];
__device__ float g_W0T[256 * 12];   // [j][k], k padded 11->12

__global__ void transpose_kernel(const float* __restrict__ W0,
                                 const float* __restrict__ W1,
                                 const float* __restrict__ W2) {
    int i = blockIdx.x;      // 0..255 (source row)
    int j = threadIdx.x;     // 0..255 (source col)
    g_W1T[j * 256 + i] = W1[i * 256 + j];
    g_W2T[j * 256 + i] = W2[i * 256 + j];
    if (i < 11)  g_W0T[j * 12 + i] = W0[i * 256 + j];
    if (i == 11) g_W0T[j * 12 + 11] = 0.0f;
}

// accurate-enough tanh: 2 MUFU (EX2 + RCP), abs err ~1e-7
__device__ __forceinline__ float tanh_fast(float x) {
    float xc = fminf(fmaxf(x, -15.0f), 15.0f);
    float e  = __expf(2.0f * xc);
    return __fdividef(e - 1.0f, e + 1.0f);
}

// packed f32x2 helpers
#define FMA2(d, a, b, c) \
    asm("fma.rn.f32x2 %0, %1, %2, %3;" : "=l"(d) : "l"(a), "l"(b), "l"(c))
#define BCAST2(d, s) \
    asm("mov.b64 %0, {%1, %1};" : "=l"(d) : "r"(s))
#define UNPACK2(lo, hi, s) \
    asm("mov.b64 {%0, %1}, %2;" : "=r"(lo), "=r"(hi) : "l"(s))

// swizzle: element (idx, m) lives at  idx*32 + (m ^ (4*((idx>>2)&7)))
__device__ __forceinline__ int swz_f(int idx) { return 4 * ((idx >> 2) & 7); }

#define M_TANH 0   // hout = tanh(acc + bias)
#define M_D3   1   // h3 = tanh(acc + bias); hout = W3[j] * (1 - h3^2)
#define M_BWD  2   // hout = acc * (1 - hout^2)   (in-place, hout holds forward act)

// do 16 FFMA2 for one k-step: rows packed in pairs (hA, hB), cols j0..j0+3 (wv)
#define KSTEP(hA, hB, wv)                                              \
    do {                                                               \
        unsigned long long b0, b1, b2, b3;                             \
        BCAST2(b0, __float_as_uint((wv).x));                           \
        BCAST2(b1, __float_as_uint((wv).y));                           \
        BCAST2(b2, __float_as_uint((wv).z));                           \
        BCAST2(b3, __float_as_uint((wv).w));                           \
        FMA2(acc2[0][0], (hA).x, b0, acc2[0][0]);                      \
        FMA2(acc2[1][0], (hA).y, b0, acc2[1][0]);                      \
        FMA2(acc2[2][0], (hB).x, b0, acc2[2][0]);                      \
        FMA2(acc2[3][0], (hB).y, b0, acc2[3][0]);                      \
        FMA2(acc2[0][1], (hA).x, b1, acc2[0][1]);                      \
        FMA2(acc2[1][1], (hA).y, b1, acc2[1][1]);                      \
        FMA2(acc2[2][1], (hB).x, b1, acc2[2][1]);                      \
        FMA2(acc2[3][1], (hB).y, b1, acc2[3][1]);                      \
        FMA2(acc2[0][2], (hA).x, b2, acc2[0][2]);                      \
        FMA2(acc2[1][2], (hA).y, b2, acc2[1][2]);                      \
        FMA2(acc2[2][2], (hB).x, b2, acc2[2][2]);                      \
        FMA2(acc2[3][2], (hB).y, b2, acc2[3][2]);                      \
        FMA2(acc2[0][3], (hA).x, b3, acc2[0][3]);                      \
        FMA2(acc2[1][3], (hA).y, b3, acc2[1][3]);                      \
        FMA2(acc2[2][3], (hB).x, b3, acc2[2][3]);                      \
        FMA2(acc2[3][3], (hB).y, b3, acc2[3][3]);                      \
    } while (0)

// 32x256 <- 32x256 @ 256x256 ; 256 threads, per-thread tile 8 rows x 4 cols,
// rows packed in pairs for fma.rn.f32x2. Activations transposed+swizzled in SMEM.
// Each warp starts its (circular) k-loop at a different chunk offset so the
// per-chunk memory bursts of the 16 resident warps are spread in time instead
// of hitting the per-SM L1tex queue simultaneously.
template <int MODE>
__device__ __forceinline__ void gemm256(const float* __restrict__ Wg,
                                        const float* __restrict__ bias,
                                        const float* __restrict__ w3,
                                        const float* __restrict__ hin,
                                        float* hout, int tid, int off) {
    const int tx = tid & 63, ty = tid >> 6;   // ty: 0..3
    const int j0 = tx * 4, m0 = ty * 8;
    const int fj = 4 * (tx & 7);              // swizzle for output cols (j0+c)>>2 == tx

    unsigned long long acc2[4][4];            // [row-pair][col]
#pragma unroll
    for (int p = 0; p < 4; p++)
#pragma unroll
        for (int c = 0; c < 4; c++) acc2[p][c] = 0ULL;

    const int k4_0 = off << 5;                // first chunk's k-base (off*32)
    float4 wcur[4];
#pragma unroll
    for (int kk = 0; kk < 4; kk++)
        wcur[kk] = *(const float4*)(Wg + (size_t)(k4_0 + kk) * 256 + j0);

#pragma unroll 1
    for (int ci = 0; ci < 64; ci++) {
        const int k4 = ((ci + (off << 3)) & 63) << 2;   // staggered circular order
        const int fk  = swz_f(k4);
        const int pma = m0 ^ fk;              // rows m0..m0+3 (this chunk)
        const int pmb = pma ^ 4;

        const int k4n = (k4 + 4) & 255;       // next chunk (wraps)
        float4 wnext[4];
#pragma unroll
        for (int kk = 0; kk < 4; kk++)
            wnext[kk] = *(const float4*)(Wg + (size_t)(k4n + kk) * 256 + j0);

#pragma unroll
        for (int kk = 0; kk < 4; kk++) {
            const float* hr = hin + (k4 + kk) * 32;
            ulonglong2 hA = *(const ulonglong2*)(hr + pma);   // pairs (m0,m0+1),(m0+2,m0+3)
            ulonglong2 hB = *(const ulonglong2*)(hr + pmb);   // pairs (m0+4,..),(m0+6,..)
            KSTEP(hA, hB, wcur[kk]);
        }
#pragma unroll
        for (int kk = 0; kk < 4; kk++) wcur[kk] = wnext[kk];
    }

    // unpack accumulators: vals[c][r] for rows m0+r
    float vals[4][8];
#pragma unroll
    for (int p = 0; p < 4; p++)
#pragma unroll
        for (int c = 0; c < 4; c++) {
            unsigned int lo, hi;
            UNPACK2(lo, hi, acc2[p][c]);
            vals[c][2 * p + 0] = __uint_as_float(lo);
            vals[c][2 * p + 1] = __uint_as_float(hi);
        }

    const int pj  = m0 ^ fj;                  // output run bases (4-aligned)
    const int pjb = pj ^ 4;

    if (MODE == M_TANH || MODE == M_D3) {
        float4 bjv = *(const float4*)(bias + j0);
        float bjc[4] = {bjv.x, bjv.y, bjv.z, bjv.w};
        float w3c[4];
        if (MODE == M_D3) {
            float4 w3v = *(const float4*)(w3 + j0);
            w3c[0] = w3v.x; w3c[1] = w3v.y; w3c[2] = w3v.z; w3c[3] = w3v.w;
        }
#pragma unroll
        for (int c = 0; c < 4; c++) {
            float z[8];
#pragma unroll
            for (int r = 0; r < 8; r++) {
                float h = tanh_fast(vals[c][r] + bjc[c]);
                z[r] = (MODE == M_TANH) ? h : (w3c[c] * (1.0f - h * h));
            }
            float* rowp = hout + (j0 + c) * 32;
            *(float4*)(rowp + pj)  = make_float4(z[0], z[1], z[2], z[3]);
            *(float4*)(rowp + pjb) = make_float4(z[4], z[5], z[6], z[7]);
        }
    } else {  // M_BWD: in-place dz = acc * (1 - h^2)
#pragma unroll
        for (int c = 0; c < 4; c++) {
            float* rowp = hout + (j0 + c) * 32;
            float4 ha = *(const float4*)(rowp + pj);
            float4 hb = *(const float4*)(rowp + pjb);
            float4 va, vb;
            va.x = vals[c][0] * (1.0f - ha.x * ha.x);
            va.y = vals[c][1] * (1.0f - ha.y * ha.y);
            va.z = vals[c][2] * (1.0f - ha.z * ha.z);
            va.w = vals[c][3] * (1.0f - ha.w * ha.w);
            vb.x = vals[c][4] * (1.0f - hb.x * hb.x);
            vb.y = vals[c][5] * (1.0f - hb.y * hb.y);
            vb.z = vals[c][6] * (1.0f - hb.z * hb.z);
            vb.w = vals[c][7] * (1.0f - hb.w * hb.w);
            *(float4*)(rowp + pj)  = va;
            *(float4*)(rowp + pjb) = vb;
        }
    }
}

__global__ void __launch_bounds__(NTHREADS, 2) ode_kernel(
    const float* __restrict__ v,  const float* __restrict__ w,
    const float* __restrict__ x,  const float* __restrict__ q,
    const float* __restrict__ W0, const float* __restrict__ b0,
    const float* __restrict__ W1, const float* __restrict__ b1,
    const float* __restrict__ W2, const float* __restrict__ b2,
    const float* __restrict__ W3,
    float* __restrict__ out) {
    extern __shared__ float smem[];
    float* h1s = smem;                    // hT layout [256][32]
    float* h2s = h1s + 256 * 32;
    float* d3s = h2s + 256 * 32;
    float* rqs = d3s + 256 * 32;          // [32][12] : r(3), qn0(4), qn1(4)
    float* grs = rqs + TILE * 12;         // [32][12] : grad_rq

    const int tid = threadIdx.x;
    const size_t row0 = (size_t)blockIdx.x * TILE;
    // warp phase offset: 8 warps x (block parity) -> 0..7, de-phases L1 bursts
    const int off = ((tid >> 5) + ((blockIdx.x & 1) << 2)) & 7;

    // ---- dxdt = v (pure copy, coalesced) ----
    if (tid < TILE * 6) {
        const size_t base = row0 * 6;
        out[(size_t)12 * Bc + base + tid] = v[base + tid];
    }

    // ---- build rq = [r, qn0, qn1] ----
    if (tid < TILE) {
        int m = tid;
        size_t g = row0 + m;
        float4 qa = *(const float4*)(q + g * 8);
        float4 qb = *(const float4*)(q + g * 8 + 4);
        float n0 = rsqrtf(qa.x * qa.x + qa.y * qa.y + qa.z * qa.z + qa.w * qa.w);
        float n1 = rsqrtf(qb.x * qb.x + qb.y * qb.y + qb.z * qb.z + qb.w * qb.w);
        const float* xp = x + g * 6;
        float* rp = rqs + m * 12;
        rp[0] = xp[3] - xp[0];
        rp[1] = xp[4] - xp[1];
        rp[2] = xp[5] - xp[2];
        rp[3] = qa.x * n0; rp[4] = qa.y * n0; rp[5] = qa.z * n0; rp[6] = qa.w * n0;
        rp[7] = qb.x * n1; rp[8] = qb.y * n1; rp[9] = qb.z * n1; rp[10] = qb.w * n1;
        rp[11] = 0.0f;
    }
    __syncthreads();

    // ---- layer 0: h1T[j][m] = tanh(rq[m] . W0[:,j] + b0[j]); one neuron per thread ----
    {
        int j = tid;
        float wcol[11];
#pragma unroll
        for (int k = 0; k < 11; k++) wcol[k] = W0[k * 256 + j];
        float bb = b0[j];
        float z[32];
#pragma unroll 4
        for (int m = 0; m < TILE; m++) {
            const float* rp = rqs + m * 12;
            float zz = bb;
#pragma unroll
            for (int k = 0; k < 11; k++) zz = fmaf(rp[k], wcol[k], zz);
            z[m] = tanh_fast(zz);
        }
        const int f = swz_f(j);
        float* rowp = h1s + j * 32;
#pragma unroll
        for (int mr = 0; mr < 32; mr += 4) {
            int pr = mr ^ f;   // 4-aligned physical base holding logical rows mr..mr+3
            *(float4*)(rowp + pr) = make_float4(z[mr], z[mr + 1], z[mr + 2], z[mr + 3]);
        }
    }
    __syncthreads();

    gemm256<M_TANH>(W1, b1, nullptr, h1s, h2s, tid, off);         // h2 = tanh(h1 W1 + b1)
    __syncthreads();
    gemm256<M_D3>(W2, b2, W3, h2s, d3s, tid, off);                // dz3 = W3*(1-h3^2)
    __syncthreads();
    gemm256<M_BWD>(g_W2T, nullptr, nullptr, d3s, h2s, tid, off);  // dz2 (in-place over h2)
    __syncthreads();
    gemm256<M_BWD>(g_W1T, nullptr, nullptr, h2s, h1s, tid, off);  // dz1 (in-place over h1)
    __syncthreads();

    // ---- grad_rq[k] = sum_j W0[k][j] * dz1[j] ; 8 threads per row ----
    {
        int m = tid >> 3, kq = tid & 7;
        float a[11];
#pragma unroll
        for (int k = 0; k < 11; k++) a[k] = 0.0f;
        int jb = kq * 32;
#pragma unroll 4
        for (int j = jb; j < jb + 32; j++) {
            float d = h1s[j * 32 + (m ^ swz_f(j))];
            float4 wA = *(const float4*)(g_W0T + j * 12);
            float4 wB = *(const float4*)(g_W0T + j * 12 + 4);
            float4 wC = *(const float4*)(g_W0T + j * 12 + 8);
            a[0] = fmaf(d, wA.x, a[0]); a[1] = fmaf(d, wA.y, a[1]);
            a[2] = fmaf(d, wA.z, a[2]); a[3] = fmaf(d, wA.w, a[3]);
            a[4] = fmaf(d, wB.x, a[4]); a[5] = fmaf(d, wB.y, a[5]);
            a[6] = fmaf(d, wB.z, a[6]); a[7] = fmaf(d, wB.w, a[7]);
            a[8] = fmaf(d, wC.x, a[8]); a[9] = fmaf(d, wC.y, a[9]);
            a[10] = fmaf(d, wC.z, a[10]);
        }
#pragma unroll
        for (int k = 0; k < 11; k++) {
            a[k] += __shfl_xor_sync(0xffffffffu, a[k], 1);
            a[k] += __shfl_xor_sync(0xffffffffu, a[k], 2);
            a[k] += __shfl_xor_sync(0xffffffffu, a[k], 4);
        }
        if (kq == 0) {
#pragma unroll
            for (int k = 0; k < 11; k++) grs[m * 12 + k] = a[k];
        }
    }
    __syncthreads();

    // ---- epilogue: quaternion dynamics + outputs (one thread per (row, particle)) ----
    if (tid < TILE * 2) {
        int m = tid >> 1, p = tid & 1;
        size_t g = row0 + m;
        size_t e = g * 2 + p;
        const float* rp = rqs + m * 12;
        const float* gp = grs + m * 12;
        float q0 = rp[3 + 4 * p], q1 = rp[4 + 4 * p], q2 = rp[5 + 4 * p], q3 = rp[6 + 4 * p];
        float gq0 = gp[3 + 4 * p], gq1 = gp[4 + 4 * p], gq2 = gp[5 + 4 * p], gq3 = gp[6 + 4 * p];
        float wx = w[e * 3 + 0], wy = w[e * 3 + 1], wz = w[e * 3 + 2];

        // dqdt = 0.5 * qn * (0, w)   (real-first Hamilton product)
        float dq0 = -0.5f * (q1 * wx + q2 * wy + q3 * wz);
        float dq1 =  0.5f * (q0 * wx + q2 * wz - q3 * wy);
        float dq2 =  0.5f * (q0 * wy - q1 * wz + q3 * wx);
        float dq3 =  0.5f * (q0 * wz + q1 * wy - q2 * wx);
        out[(size_t)18 * Bc + e * 4 + 0] = dq0;
        out[(size_t)18 * Bc + e * 4 + 1] = dq1;
        out[(size_t)18 * Bc + e * 4 + 2] = dq2;
        out[(size_t)18 * Bc + e * 4 + 3] = dq3;

        float Gq[3][4] = {{-q1,  q0,  q3, -q2},
                          {-q2, -q3,  q0,  q1},
                          {-q3,  q2, -q1,  q0}};
        float Gd[3][4] = {{-dq1,  dq0,  dq3, -dq2},
                          {-dq2, -dq3,  dq0,  dq1},
                          {-dq3,  dq2, -dq1,  dq0}};
        float l0 = wx * 1.0f, l1 = wy * 2.0f, l2 = wz * 3.0f;
        float gqv[4] = {gq0, gq1, gq2, gq3};
#pragma unroll
        for (int i = 0; i < 3; i++) {
            float O0 = 2.0f * (Gq[i][0] * Gd[0][0] + Gq[i][1] * Gd[0][1] + Gq[i][2] * Gd[0][2] + Gq[i][3] * Gd[0][3]);
            float O1 = 2.0f * (Gq[i][0] * Gd[1][0] + Gq[i][1] * Gd[1][1] + Gq[i][2] * Gd[1][2] + Gq[i][3] * Gd[1][3]);
            float O2 = 2.0f * (Gq[i][0] * Gd[2][0] + Gq[i][1] * Gd[2][1] + Gq[i][2] * Gd[2][2] + Gq[i][3] * Gd[2][3]);
            float t = -(O0 * l0 + O1 * l1 + O2 * l2)
                      - 0.5f * (Gq[i][0] * gqv[0] + Gq[i][1] * gqv[1] + Gq[i][2] * gqv[2] + Gq[i][3] * gqv[3]);
            out[(size_t)6 * Bc + e * 3 + i] = t / (float)(i + 1);
        }

        // dvdt = +-(grad_r + harm)/MASS
        float r0 = rp[0], r1 = rp[1], r2 = rp[2];
        float rn = sqrtf(r0 * r0 + r1 * r1 + r2 * r2);
        float coef = 100.0f * (rn - 1.0f) / rn;
        float sgn = p ? -1.0f : 1.0f;
        out[e * 3 + 0] = sgn * (gp[0] + coef * r0) / 7.0f;
        out[e * 3 + 1] = sgn * (gp[1] + coef * r1) / 7.0f;
        out[e * 3 + 2] = sgn * (gp[2] + coef * r2) / 7.0f;
    }
}

extern "C" void kernel_launch(void* const* d_in, const int* in_sizes, int n_in,
                              void* d_out, int out_size) {
    const float* v  = (const float*)d_in[0];
    const float* w  = (const float*)d_in[1];
    const float* x  = (const float*)d_in[2];
    const float* q  = (const float*)d_in[3];
    const float* W0 = (const float*)d_in[4];
    const float* b0 = (const float*)d_in[5];
    const float* W1 = (const float*)d_in[6];
    const float* b1 = (const float*)d_in[7];
    const float* W2 = (const float*)d_in[8];
    const float* b2 = (const float*)d_in[9];
    const float* W3 = (const float*)d_in[10];
    float* out = (float*)d_out;

    constexpr size_t SMEM_BYTES = (size_t)(3 * 256 * 32 + 2 * TILE * 12) * sizeof(float);
    cudaFuncSetAttribute(ode_kernel, cudaFuncAttributeMaxDynamicSharedMemorySize,
                         (int)SMEM_BYTES);

    transpose_kernel<<<256, 256>>>(W0, W1, W2);
    ode_kernel<<<Bc / TILE, NTHREADS, SMEM_BYTES>>>(v, w, x, q, W0, b0, W1, b1,
                                                    W2, b2, W3, out);
}

// round 13
// speedup vs baseline: 1.1414x; 1.1056x over previous
#include <cuda_runtime.h>
#include <cstdint>

#define Bc      131072
#define TILE    32
#define NTHREADS 128
// transposed activation layout: hT[k][m], k=0..255, m=0..31 (32 floats/row, swizzled)

typedef unsigned long long ULL;

// ---------------- device scratch (no allocations allowed) ----------------
__device__ float g_W1T[256 * 256];
__device__ float g_W2T[256 * 256];
__device__ float g_W0T[256 * 12];   // [j][k], k padded 11->12

__global__ void transpose_kernel(const float* __restrict__ W0,
                                 const float* __restrict__ W1,
                                 const float* __restrict__ W2) {
    int i = blockIdx.x;      // 0..255 (source row)
    int j = threadIdx.x;     // 0..255 (source col)
    g_W1T[j * 256 + i] = W1[i * 256 + j];
    g_W2T[j * 256 + i] = W2[i * 256 + j];
    if (i < 11)  g_W0T[j * 12 + i] = W0[i * 256 + j];
    if (i == 11) g_W0T[j * 12 + 11] = 0.0f;
}

// accurate-enough tanh: 2 MUFU (EX2 + RCP), abs err ~1e-7
__device__ __forceinline__ float tanh_fast(float x) {
    float xc = fminf(fmaxf(x, -15.0f), 15.0f);
    float e  = __expf(2.0f * xc);
    return __fdividef(e - 1.0f, e + 1.0f);
}

// packed f32x2 helpers
#define FMA2(d, a, b, c) \
    asm("fma.rn.f32x2 %0, %1, %2, %3;" : "=l"(d) : "l"(a), "l"(b), "l"(c))
#define BCAST2(d, s) \
    asm("mov.b64 %0, {%1, %1};" : "=l"(d) : "r"(s))
#define UNPACK2(lo, hi, s) \
    asm("mov.b64 {%0, %1}, %2;" : "=r"(lo), "=r"(hi) : "l"(s))

// swizzle: element (row, m) lives at  row*32 + (m ^ (4*((row>>3)&7)))
__device__ __forceinline__ int swz_f(int row) { return 4 * ((row >> 3) & 7); }

#define M_TANH 0   // hout = tanh(acc + bias)
#define M_D3   1   // h3 = tanh(acc + bias); hout = W3[j] * (1 - h3^2)
#define M_BWD  2   // hout = acc * (1 - hout^2)   (in-place, hout holds forward act)

// 32 FFMA2 for one k-step: row pairs in hA (m0..m0+3) / hB (m0+4..m0+7),
// 8 weight cols in wva (j0..j0+3) / wvb (j0+4..j0+7)
#define KSTEP8(hA, hB, wva, wvb)                                       \
    do {                                                               \
        ULL b0, b1, b2, b3, b4, b5, b6, b7;                            \
        BCAST2(b0, __float_as_uint((wva).x));                          \
        BCAST2(b1, __float_as_uint((wva).y));                          \
        BCAST2(b2, __float_as_uint((wva).z));                          \
        BCAST2(b3, __float_as_uint((wva).w));                          \
        BCAST2(b4, __float_as_uint((wvb).x));                          \
        BCAST2(b5, __float_as_uint((wvb).y));                          \
        BCAST2(b6, __float_as_uint((wvb).z));                          \
        BCAST2(b7, __float_as_uint((wvb).w));                          \
        FMA2(acc2[0][0], (hA).x, b0, acc2[0][0]);                      \
        FMA2(acc2[1][0], (hA).y, b0, acc2[1][0]);                      \
        FMA2(acc2[2][0], (hB).x, b0, acc2[2][0]);                      \
        FMA2(acc2[3][0], (hB).y, b0, acc2[3][0]);                      \
        FMA2(acc2[0][1], (hA).x, b1, acc2[0][1]);                      \
        FMA2(acc2[1][1], (hA).y, b1, acc2[1][1]);                      \
        FMA2(acc2[2][1], (hB).x, b1, acc2[2][1]);                      \
        FMA2(acc2[3][1], (hB).y, b1, acc2[3][1]);                      \
        FMA2(acc2[0][2], (hA).x, b2, acc2[0][2]);                      \
        FMA2(acc2[1][2], (hA).y, b2, acc2[1][2]);                      \
        FMA2(acc2[2][2], (hB).x, b2, acc2[2][2]);                      \
        FMA2(acc2[3][2], (hB).y, b2, acc2[3][2]);                      \
        FMA2(acc2[0][3], (hA).x, b3, acc2[0][3]);                      \
        FMA2(acc2[1][3], (hA).y, b3, acc2[1][3]);                      \
        FMA2(acc2[2][3], (hB).x, b3, acc2[2][3]);                      \
        FMA2(acc2[3][3], (hB).y, b3, acc2[3][3]);                      \
        FMA2(acc2[0][4], (hA).x, b4, acc2[0][4]);                      \
        FMA2(acc2[1][4], (hA).y, b4, acc2[1][4]);                      \
        FMA2(acc2[2][4], (hB).x, b4, acc2[2][4]);                      \
        FMA2(acc2[3][4], (hB).y, b4, acc2[3][4]);                      \
        FMA2(acc2[0][5], (hA).x, b5, acc2[0][5]);                      \
        FMA2(acc2[1][5], (hA).y, b5, acc2[1][5]);                      \
        FMA2(acc2[2][5], (hB).x, b5, acc2[2][5]);                      \
        FMA2(acc2[3][5], (hB).y, b5, acc2[3][5]);                      \
        FMA2(acc2[0][6], (hA).x, b6, acc2[0][6]);                      \
        FMA2(acc2[1][6], (hA).y, b6, acc2[1][6]);                      \
        FMA2(acc2[2][6], (hB).x, b6, acc2[2][6]);                      \
        FMA2(acc2[3][6], (hB).y, b6, acc2[3][6]);                      \
        FMA2(acc2[0][7], (hA).x, b7, acc2[0][7]);                      \
        FMA2(acc2[1][7], (hA).y, b7, acc2[1][7]);                      \
        FMA2(acc2[2][7], (hB).x, b7, acc2[2][7]);                      \
        FMA2(acc2[3][7], (hB).y, b7, acc2[3][7]);                      \
    } while (0)

// 32x256 <- 32x256 @ 256x256 ; 128 threads, per-thread tile 8 rows x 8 cols.
// 1.0 B/MAC of L1 traffic (vs 1.5 for 8x4) -> L1 data-path and FMA pipe balanced.
template <int MODE>
__device__ __forceinline__ void gemm256(const float* __restrict__ Wg,
                                        const float* __restrict__ bias,
                                        const float* __restrict__ w3,
                                        const float* __restrict__ hin,
                                        float* hout, int tid) {
    const int tx = tid & 31, ty = tid >> 5;   // ty: 0..3
    const int j0 = tx * 8, m0 = ty * 8;

    ULL acc2[4][8];                           // [row-pair][col]
#pragma unroll
    for (int p = 0; p < 4; p++)
#pragma unroll
        for (int c = 0; c < 8; c++) acc2[p][c] = 0ULL;

    float4 wcA[4], wcB[4];
#pragma unroll
    for (int kk = 0; kk < 4; kk++) {
        wcA[kk] = *(const float4*)(Wg + (size_t)kk * 256 + j0);
        wcB[kk] = *(const float4*)(Wg + (size_t)kk * 256 + j0 + 4);
    }

#pragma unroll 1
    for (int k4 = 0; k4 < 256; k4 += 4) {
        const int fk  = swz_f(k4);            // constant within the 4-chunk
        const int pma = m0 ^ fk;
        const int pmb = pma ^ 4;

        const int k4n = (k4 + 4) & 255;       // in-bounds wrap
        float4 wnA[4], wnB[4];
#pragma unroll
        for (int kk = 0; kk < 4; kk++) {
            wnA[kk] = *(const float4*)(Wg + (size_t)(k4n + kk) * 256 + j0);
            wnB[kk] = *(const float4*)(Wg + (size_t)(k4n + kk) * 256 + j0 + 4);
        }

#pragma unroll
        for (int kk = 0; kk < 4; kk++) {
            const float* hr = hin + (k4 + kk) * 32;
            ulonglong2 hA = *(const ulonglong2*)(hr + pma);   // rows m0..m0+3
            ulonglong2 hB = *(const ulonglong2*)(hr + pmb);   // rows m0+4..m0+7
            KSTEP8(hA, hB, wcA[kk], wcB[kk]);
        }
#pragma unroll
        for (int kk = 0; kk < 4; kk++) { wcA[kk] = wnA[kk]; wcB[kk] = wnB[kk]; }
    }

    // unpack accumulators: vals[c][r] for rows m0+r
    float vals[8][8];
#pragma unroll
    for (int p = 0; p < 4; p++)
#pragma unroll
        for (int c = 0; c < 8; c++) {
            unsigned int lo, hi;
            UNPACK2(lo, hi, acc2[p][c]);
            vals[c][2 * p + 0] = __uint_as_float(lo);
            vals[c][2 * p + 1] = __uint_as_float(hi);
        }

    // writer offset: rows j0..j0+7 all have (row>>3)==tx -> f = 4*(tx&7)
    const int pj  = m0 ^ (4 * (tx & 7));
    const int pjb = pj ^ 4;

    if (MODE == M_TANH || MODE == M_D3) {
        float bj[8];
        {
            float4 a = *(const float4*)(bias + j0);
            float4 b = *(const float4*)(bias + j0 + 4);
            bj[0] = a.x; bj[1] = a.y; bj[2] = a.z; bj[3] = a.w;
            bj[4] = b.x; bj[5] = b.y; bj[6] = b.z; bj[7] = b.w;
        }
        float w3c[8];
        if (MODE == M_D3) {
            float4 a = *(const float4*)(w3 + j0);
            float4 b = *(const float4*)(w3 + j0 + 4);
            w3c[0] = a.x; w3c[1] = a.y; w3c[2] = a.z; w3c[3] = a.w;
            w3c[4] = b.x; w3c[5] = b.y; w3c[6] = b.z; w3c[7] = b.w;
        }
#pragma unroll
        for (int c = 0; c < 8; c++) {
            float z[8];
#pragma unroll
            for (int r = 0; r < 8; r++) {
                float h = tanh_fast(vals[c][r] + bj[c]);
                z[r] = (MODE == M_TANH) ? h : (w3c[c] * (1.0f - h * h));
            }
            float* rowp = hout + (j0 + c) * 32;
            *(float4*)(rowp + pj)  = make_float4(z[0], z[1], z[2], z[3]);
            *(float4*)(rowp + pjb) = make_float4(z[4], z[5], z[6], z[7]);
        }
    } else {  // M_BWD: in-place dz = acc * (1 - h^2)
#pragma unroll
        for (int c = 0; c < 8; c++) {
            float* rowp = hout + (j0 + c) * 32;
            float4 ha = *(const float4*)(rowp + pj);
            float4 hb = *(const float4*)(rowp + pjb);
            float4 va, vb;
            va.x = vals[c][0] * (1.0f - ha.x * ha.x);
            va.y = vals[c][1] * (1.0f - ha.y * ha.y);
            va.z = vals[c][2] * (1.0f - ha.z * ha.z);
            va.w = vals[c][3] * (1.0f - ha.w * ha.w);
            vb.x = vals[c][4] * (1.0f - hb.x * hb.x);
            vb.y = vals[c][5] * (1.0f - hb.y * hb.y);
            vb.z = vals[c][6] * (1.0f - hb.z * hb.z);
            vb.w = vals[c][7] * (1.0f - hb.w * hb.w);
            *(float4*)(rowp + pj)  = va;
            *(float4*)(rowp + pjb) = vb;
        }
    }
}

__global__ void __launch_bounds__(NTHREADS, 2) ode_kernel(
    const float* __restrict__ v,  const float* __restrict__ w,
    const float* __restrict__ x,  const float* __restrict__ q,
    const float* __restrict__ W0, const float* __restrict__ b0,
    const float* __restrict__ W1, const float* __restrict__ b1,
    const float* __restrict__ W2, const float* __restrict__ b2,
    const float* __restrict__ W3,
    float* __restrict__ out) {
    extern __shared__ float smem[];
    float* h1s = smem;                    // hT layout [256][32]
    float* h2s = h1s + 256 * 32;
    float* d3s = h2s + 256 * 32;
    float* rqs = d3s + 256 * 32;          // [32][12] : r(3), qn0(4), qn1(4)
    float* grs = rqs + TILE * 12;         // [32][12] : grad_rq

    const int tid = threadIdx.x;
    const size_t row0 = (size_t)blockIdx.x * TILE;

    // ---- dxdt = v (pure copy, coalesced) ----
    {
        const size_t base = row0 * 6;
#pragma unroll
        for (int i = 0; i < 2; i++) {
            int idx = tid + i * NTHREADS;
            if (idx < TILE * 6)
                out[(size_t)12 * Bc + base + idx] = v[base + idx];
        }
    }

    // ---- build rq = [r, qn0, qn1] ----
    if (tid < TILE) {
        int m = tid;
        size_t g = row0 + m;
        float4 qa = *(const float4*)(q + g * 8);
        float4 qb = *(const float4*)(q + g * 8 + 4);
        float n0 = rsqrtf(qa.x * qa.x + qa.y * qa.y + qa.z * qa.z + qa.w * qa.w);
        float n1 = rsqrtf(qb.x * qb.x + qb.y * qb.y + qb.z * qb.z + qb.w * qb.w);
        const float* xp = x + g * 6;
        float* rp = rqs + m * 12;
        rp[0] = xp[3] - xp[0];
        rp[1] = xp[4] - xp[1];
        rp[2] = xp[5] - xp[2];
        rp[3] = qa.x * n0; rp[4] = qa.y * n0; rp[5] = qa.z * n0; rp[6] = qa.w * n0;
        rp[7] = qb.x * n1; rp[8] = qb.y * n1; rp[9] = qb.z * n1; rp[10] = qb.w * n1;
        rp[11] = 0.0f;
    }
    __syncthreads();

    // ---- layer 0: h1T[j][m] = tanh(rq[m].W0[:,j] + b0[j]); 2 neurons per thread ----
    {
#pragma unroll
        for (int jj = 0; jj < 2; jj++) {
            int j = tid + jj * NTHREADS;
            float wcol[11];
#pragma unroll
            for (int k = 0; k < 11; k++) wcol[k] = W0[k * 256 + j];
            float bb = b0[j];
            float z[32];
#pragma unroll 4
            for (int m = 0; m < TILE; m++) {
                const float* rp = rqs + m * 12;
                float zz = bb;
#pragma unroll
                for (int k = 0; k < 11; k++) zz = fmaf(rp[k], wcol[k], zz);
                z[m] = tanh_fast(zz);
            }
            const int f = swz_f(j);
            float* rowp = h1s + j * 32;
#pragma unroll
            for (int mr = 0; mr < 32; mr += 4) {
                int pr = mr ^ f;
                *(float4*)(rowp + pr) = make_float4(z[mr], z[mr + 1], z[mr + 2], z[mr + 3]);
            }
        }
    }
    __syncthreads();

    gemm256<M_TANH>(W1, b1, nullptr, h1s, h2s, tid);         // h2 = tanh(h1 W1 + b1)
    __syncthreads();
    gemm256<M_D3>(W2, b2, W3, h2s, d3s, tid);                // dz3 = W3*(1-h3^2)
    __syncthreads();
    gemm256<M_BWD>(g_W2T, nullptr, nullptr, d3s, h2s, tid);  // dz2 (in-place over h2)
    __syncthreads();
    gemm256<M_BWD>(g_W1T, nullptr, nullptr, h2s, h1s, tid);  // dz1 (in-place over h1)
    __syncthreads();

    // ---- grad_rq[k] = sum_j W0[k][j] * dz1[j] ; 4 threads per row ----
    {
        int m = tid >> 2, kq = tid & 3;
        float a[11];
#pragma unroll
        for (int k = 0; k < 11; k++) a[k] = 0.0f;
        int jb = kq * 64;
#pragma unroll 4
        for (int j = jb; j < jb + 64; j++) {
            float d = h1s[j * 32 + (m ^ swz_f(j))];
            float4 wA = *(const float4*)(g_W0T + j * 12);
            float4 wB = *(const float4*)(g_W0T + j * 12 + 4);
            float4 wC = *(const float4*)(g_W0T + j * 12 + 8);
            a[0] = fmaf(d, wA.x, a[0]); a[1] = fmaf(d, wA.y, a[1]);
            a[2] = fmaf(d, wA.z, a[2]); a[3] = fmaf(d, wA.w, a[3]);
            a[4] = fmaf(d, wB.x, a[4]); a[5] = fmaf(d, wB.y, a[5]);
            a[6] = fmaf(d, wB.z, a[6]); a[7] = fmaf(d, wB.w, a[7]);
            a[8] = fmaf(d, wC.x, a[8]); a[9] = fmaf(d, wC.y, a[9]);
            a[10] = fmaf(d, wC.z, a[10]);
        }
#pragma unroll
        for (int k = 0; k < 11; k++) {
            a[k] += __shfl_xor_sync(0xffffffffu, a[k], 1);
            a[k] += __shfl_xor_sync(0xffffffffu, a[k], 2);
        }
        if (kq == 0) {
#pragma unroll
            for (int k = 0; k < 11; k++) grs[m * 12 + k] = a[k];
        }
    }
    __syncthreads();

    // ---- epilogue: quaternion dynamics + outputs (one thread per (row, particle)) ----
    if (tid < TILE * 2) {
        int m = tid >> 1, p = tid & 1;
        size_t g = row0 + m;
        size_t e = g * 2 + p;
        const float* rp = rqs + m * 12;
        const float* gp = grs + m * 12;
        float q0 = rp[3 + 4 * p], q1 = rp[4 + 4 * p], q2 = rp[5 + 4 * p], q3 = rp[6 + 4 * p];
        float gq0 = gp[3 + 4 * p], gq1 = gp[4 + 4 * p], gq2 = gp[5 + 4 * p], gq3 = gp[6 + 4 * p];
        float wx = w[e * 3 + 0], wy = w[e * 3 + 1], wz = w[e * 3 + 2];

        // dqdt = 0.5 * qn * (0, w)   (real-first Hamilton product)
        float dq0 = -0.5f * (q1 * wx + q2 * wy + q3 * wz);
        float dq1 =  0.5f * (q0 * wx + q2 * wz - q3 * wy);
        float dq2 =  0.5f * (q0 * wy - q1 * wz + q3 * wx);
        float dq3 =  0.5f * (q0 * wz + q1 * wy - q2 * wx);
        out[(size_t)18 * Bc + e * 4 + 0] = dq0;
        out[(size_t)18 * Bc + e * 4 + 1] = dq1;
        out[(size_t)18 * Bc + e * 4 + 2] = dq2;
        out[(size_t)18 * Bc + e * 4 + 3] = dq3;

        float Gq[3][4] = {{-q1,  q0,  q3, -q2},
                          {-q2, -q3,  q0,  q1},
                          {-q3,  q2, -q1,  q0}};
        float Gd[3][4] = {{-dq1,  dq0,  dq3, -dq2},
                          {-dq2, -dq3,  dq0,  dq1},
                          {-dq3,  dq2, -dq1,  dq0}};
        float l0 = wx * 1.0f, l1 = wy * 2.0f, l2 = wz * 3.0f;
        float gqv[4] = {gq0, gq1, gq2, gq3};
#pragma unroll
        for (int i = 0; i < 3; i++) {
            float O0 = 2.0f * (Gq[i][0] * Gd[0][0] + Gq[i][1] * Gd[0][1] + Gq[i][2] * Gd[0][2] + Gq[i][3] * Gd[0][3]);
            float O1 = 2.0f * (Gq[i][0] * Gd[1][0] + Gq[i][1] * Gd[1][1] + Gq[i][2] * Gd[1][2] + Gq[i][3] * Gd[1][3]);
            float O2 = 2.0f * (Gq[i][0] * Gd[2][0] + Gq[i][1] * Gd[2][1] + Gq[i][2] * Gd[2][2] + Gq[i][3] * Gd[2][3]);
            float t = -(O0 * l0 + O1 * l1 + O2 * l2)
                      - 0.5f * (Gq[i][0] * gqv[0] + Gq[i][1] * gqv[1] + Gq[i][2] * gqv[2] + Gq[i][3] * gqv[3]);
            out[(size_t)6 * Bc + e * 3 + i] = t / (float)(i + 1);
        }

        // dvdt = +-(grad_r + harm)/MASS
        float r0 = rp[0], r1 = rp[1], r2 = rp[2];
        float rn = sqrtf(r0 * r0 + r1 * r1 + r2 * r2);
        float coef = 100.0f * (rn - 1.0f) / rn;
        float sgn = p ? -1.0f : 1.0f;
        out[e * 3 + 0] = sgn * (gp[0] + coef * r0) / 7.0f;
        out[e * 3 + 1] = sgn * (gp[1] + coef * r1) / 7.0f;
        out[e * 3 + 2] = sgn * (gp[2] + coef * r2) / 7.0f;
    }
}

extern "C" void kernel_launch(void* const* d_in, const int* in_sizes, int n_in,
                              void* d_out, int out_size) {
    const float* v  = (const float*)d_in[0];
    const float* w  = (const float*)d_in[1];
    const float* x  = (const float*)d_in[2];
    const float* q  = (const float*)d_in[3];
    const float* W0 = (const float*)d_in[4];
    const float* b0 = (const float*)d_in[5];
    const float* W1 = (const float*)d_in[6];
    const float* b1 = (const float*)d_in[7];
    const float* W2 = (const float*)d_in[8];
    const float* b2 = (const float*)d_in[9];
    const float* W3 = (const float*)d_in[10];
    float* out = (float*)d_out;

    constexpr size_t SMEM_BYTES = (size_t)(3 * 256 * 32 + 2 * TILE * 12) * sizeof(float);
    cudaFuncSetAttribute(ode_kernel, cudaFuncAttributeMaxDynamicSharedMemorySize,
                         (int)SMEM_BYTES);

    transpose_kernel<<<256, 256>>>(W0, W1, W2);
    ode_kernel<<<Bc / TILE, NTHREADS, SMEM_BYTES>>>(v, w, x, q, W0, b0, W1, b1,
                                                    W2, b2, W3, out);
}